// round 3
// baseline (speedup 1.0000x reference)
#include <cuda_runtime.h>
#include <cuda_bf16.h>
#include <cub/cub.cuh>
#include <math.h>

#define NTOT 65536
#define L_CH 512
#define WARMUP 512
#define NCH (NTOT / L_CH)   // 128

// ---------------- static scratch (no allocations allowed) ----------------
__device__ unsigned int g_keys[NTOT];
__device__ unsigned int g_keys2[NTOT];
__device__ unsigned int g_idx[NTOT];
__device__ unsigned int g_idx2[NTOT];
__device__ unsigned char g_cubtemp[1 << 23];   // 8 MB, plenty for 64K pairs
__device__ float g_x[NTOT * 8];                // sorted-order features
__device__ float g_ys[2 * NTOT * 16];          // raw scan outputs (dir, sortedpos, i)
__device__ float g_ctx[2 * NTOT * 8];          // fwd/bwd ctx in ORIGINAL order

// ---------------- kernel 1: sort keys ----------------
__global__ void prep_kernel(const float* __restrict__ g,
                            unsigned int* __restrict__ keys,
                            unsigned int* __restrict__ vals) {
    int n = blockIdx.x * blockDim.x + threadIdx.x;
    keys[n] = __float_as_uint(g[n]) & 0x7fffffffu;  // |g| bits sort as uint
    vals[n] = (unsigned)n;
}

// ---------------- kernel 2: x = [gs, ss] @ inproj_W.T + b (sorted order) ----------------
__global__ void xproj_kernel(const float* __restrict__ g, const float* __restrict__ s,
                             const unsigned int* __restrict__ sidx,
                             const float* __restrict__ W, const float* __restrict__ b,
                             float* __restrict__ x) {
    int k = blockIdx.x * blockDim.x + threadIdx.x;
    int o = sidx[k];
    float gv = g[o], sv = s[o];
#pragma unroll
    for (int m = 0; m < 8; m++)
        x[k * 8 + m] = fmaf(gv, W[m * 2 + 0], fmaf(sv, W[m * 2 + 1], b[m]));
}

// ---------------- kernel 3: chunked warmup Mamba scan (both directions) ----------------
__global__ void __launch_bounds__(256) scan_kernel(
    const float* __restrict__ x,
    const float* __restrict__ inW,   // (2,32,8)
    const float* __restrict__ dtW,   // (2,16,16)
    const float* __restrict__ dtb,   // (2,16)
    const float* __restrict__ BW,    // (2,16,16)
    const float* __restrict__ CW,    // (2,16,16)
    const float* __restrict__ Alog,  // (2,16,16)
    const float* __restrict__ rope,  // (2,16,16)
    const float* __restrict__ h0f, const float* __restrict__ h0b,
    float* __restrict__ ys,          // (2,N,16)
    float* __restrict__ hfin)        // 512 floats: new_fwd then new_bwd
{
    const int dir = blockIdx.y;
    const int chunk = blockIdx.x;
    const int tid = threadIdx.x;
    const int i = tid >> 4, j = tid & 15;
    const int lane = tid & 31;
    const int srcRot = (lane & 16) | ((lane + 15) & 15);  // j-1 mod 16 within 16-lane group

    __shared__ float s_inWx[8][16];   // [m][i]
    __shared__ float s_dtWT[16][16];  // [k][i]
    __shared__ float s_BWT[16][16];   // [k][j]
    __shared__ float s_CWT[16][16];
    __shared__ float s_dtb[16];
    __shared__ float sx[16][8];
    __shared__ float sxb[16][16];
    __shared__ float sdt[16][16];
    __shared__ float sdxb[16][16];
    __shared__ float sB[16][16];
    __shared__ float sC[16][16];
    __shared__ float sy[16][16];

    if (tid < 128) { int m = tid >> 4, c = tid & 15; s_inWx[m][c] = inW[dir * 256 + c * 8 + m]; }
    { int k = tid >> 4, c = tid & 15;
      s_dtWT[k][c] = dtW[dir * 256 + c * 16 + k];
      s_BWT[k][c]  = BW [dir * 256 + c * 16 + k];
      s_CWT[k][c]  = CW [dir * 256 + c * 16 + k]; }
    if (tid < 16) s_dtb[tid] = dtb[dir * 16 + tid];

    const float Ac = -__expf(Alog[dir * 256 + tid]);
    const float Rc = rope[dir * 256 + tid];

    int g0 = chunk * L_CH - WARMUP;
    float h;
    if (g0 <= 0) { g0 = 0; h = (dir == 0 ? h0f : h0b)[tid]; }  // exact initial state
    else h = 0.0f;                                             // warmup (state decays)
    const int gend = (chunk + 1) * L_CH;
    const int outStart = chunk * L_CH;

    __syncthreads();

    for (int base = g0; base < gend; base += 16) {
        if (tid < 128) {  // stage inputs
            int t = tid >> 3, m = tid & 7;
            int p = (dir == 0) ? (base + t) : (NTOT - 1 - (base + t));
            sx[t][m] = x[p * 8 + m];
        }
        __syncthreads();
        {   // xb projection
            int t = tid >> 4, c = tid & 15;
            float acc = 0.0f;
#pragma unroll
            for (int m = 0; m < 8; m++) acc = fmaf(sx[t][m], s_inWx[m][c], acc);
            sxb[t][c] = acc;
        }
        __syncthreads();
        {   // dt / B / C projections
            int t = tid >> 4, c = tid & 15;
            float u = s_dtb[c], bv = 0.0f, cv = 0.0f;
#pragma unroll
            for (int k = 0; k < 16; k++) {
                float xbk = sxb[t][k];
                u  = fmaf(xbk, s_dtWT[k][c], u);
                bv = fmaf(xbk, s_BWT[k][c], bv);
                cv = fmaf(xbk, s_CWT[k][c], cv);
            }
            float dt = (u > 15.0f) ? u : log1pf(__expf(u));  // softplus
            sdt[t][c] = dt;
            sdxb[t][c] = dt * sxb[t][c];
            sB[t][c] = bv; sC[t][c] = cv;
        }
        __syncthreads();
        // sequential recurrence, 16 micro-steps
#pragma unroll
        for (int t = 0; t < 16; t++) {
            float dt  = sdt[t][i];
            float dxb = sdxb[t][i];
            float Bv  = sB[t][j];
            float Cv  = sC[t][j];
            float ph = dt * Rc;
            float p2 = ph * ph;
            // sin/cos Taylor (|ph| << 1): 4 terms each
            float sn = fmaf(p2, -1.0f / 5040.0f, 1.0f / 120.0f);
            sn = fmaf(p2, sn, -1.0f / 6.0f);
            sn = ph * fmaf(p2, sn, 1.0f);
            float cs = fmaf(p2, -1.0f / 720.0f, 1.0f / 24.0f);
            cs = fmaf(p2, cs, -0.5f);
            cs = fmaf(p2, cs, 1.0f);
            float xA  = dt * Ac;
            float num = fmaf(0.5f, xA, 1.0f);
            float den = fmaf(-0.5f, xA, 1.0f + 1e-8f);
            float ab  = __fdividef(num, den);
            float hm1 = __shfl_sync(0xffffffffu, h, srcRot);
            float ca = ab * cs, cb = ab * sn;
            h = fmaf(ca, h, fmaf(-cb, hm1, dxb * Bv));
            float y = h * Cv;
            y += __shfl_xor_sync(0xffffffffu, y, 8);
            y += __shfl_xor_sync(0xffffffffu, y, 4);
            y += __shfl_xor_sync(0xffffffffu, y, 2);
            y += __shfl_xor_sync(0xffffffffu, y, 1);
            if (j == 0) sy[t][i] = y;
        }
        __syncthreads();
        if (base >= outStart) {
            int t = tid >> 4, ii = tid & 15;
            int p = (dir == 0) ? (base + t) : (NTOT - 1 - (base + t));
            ys[((size_t)dir * NTOT + p) * 16 + ii] = sy[t][ii];
        }
        __syncthreads();
    }
    if (chunk == NCH - 1) hfin[dir * 256 + tid] = h;  // final states (outputs)
}

// ---------------- kernel 4: epilogue projections + scatter to original order ----------------
__global__ void post_kernel(const float* __restrict__ x, const float* __restrict__ ys,
                            const unsigned int* __restrict__ sidx,
                            const float* __restrict__ inW, const float* __restrict__ D,
                            const float* __restrict__ outW, float* __restrict__ ctx) {
    int k = blockIdx.x * blockDim.x + threadIdx.x;
    float xv[8];
#pragma unroll
    for (int m = 0; m < 8; m++) xv[m] = x[k * 8 + m];
    int o = sidx[k];
#pragma unroll
    for (int d = 0; d < 2; d++) {
        float out[8];
#pragma unroll
        for (int m = 0; m < 8; m++) out[m] = 0.0f;
#pragma unroll
        for (int ii = 0; ii < 16; ii++) {
            float xb = 0.0f, z = 0.0f;
#pragma unroll
            for (int m = 0; m < 8; m++) {
                xb = fmaf(xv[m], inW[d * 256 + ii * 8 + m], xb);
                z  = fmaf(xv[m], inW[d * 256 + (16 + ii) * 8 + m], z);
            }
            float sg = __fdividef(1.0f, 1.0f + __expf(-z));
            float yi = fmaf(ys[((size_t)d * NTOT + k) * 16 + ii], z * sg,
                            D[d * 16 + ii] * xb);
#pragma unroll
            for (int m = 0; m < 8; m++)
                out[m] = fmaf(yi, outW[d * 128 + m * 16 + ii], out[m]);
        }
#pragma unroll
        for (int m = 0; m < 8; m++) ctx[((size_t)d * NTOT + o) * 8 + m] = out[m];
    }
}

// ---------------- kernel 5: GRU + PEER routing/experts + final combine ----------------
__global__ void __launch_bounds__(256) gp_kernel(
    const float* __restrict__ g, const float* __restrict__ s,
    const float* __restrict__ gru0, const float* __restrict__ ctx,
    const float* __restrict__ Wz, const float* __restrict__ bz,
    const float* __restrict__ Wr, const float* __restrict__ br,
    const float* __restrict__ Wh, const float* __restrict__ bh,
    const float* __restrict__ qW, const float* __restrict__ kA, const float* __restrict__ kB,
    const float* __restrict__ eW1, const float* __restrict__ eb1,
    const float* __restrict__ eW2, const float* __restrict__ eb2,
    float* __restrict__ out) {
    __shared__ float sWz[88], sWr[88], sWh[88], sbz[4], sbr[4], sbh[4];
    __shared__ float sqW[704];       // (4,8,22)
    __shared__ float skA[192], skB[192];
    __shared__ float seW1[144 * 17], seb1[144 * 17], seW2[144 * 17];  // pad vs bank conflicts
    __shared__ float seb2[144];

    int tid = threadIdx.x;
    for (int q = tid; q < 88; q += 256) { sWz[q] = Wz[q]; sWr[q] = Wr[q]; sWh[q] = Wh[q]; }
    if (tid < 4) { sbz[tid] = bz[tid]; sbr[tid] = br[tid]; sbh[tid] = bh[tid]; }
    for (int q = tid; q < 704; q += 256) sqW[q] = qW[q];
    for (int q = tid; q < 192; q += 256) { skA[q] = kA[q]; skB[q] = kB[q]; }
    for (int q = tid; q < 2304; q += 256) {
        int e = q >> 4, eh = q & 15;
        seW1[e * 17 + eh] = eW1[q];
        seb1[e * 17 + eh] = eb1[q];
        seW2[e * 17 + eh] = eW2[q];
    }
    for (int q = tid; q < 144; q += 256) seb2[q] = eb2[q];
    __syncthreads();

    int n = blockIdx.x * blockDim.x + tid;
    float gv = g[n], sv = s[n];
    float xin[18];
    xin[0] = gv; xin[1] = sv;
#pragma unroll
    for (int m = 0; m < 8; m++) { xin[2 + m] = ctx[(size_t)n * 8 + m]; xin[10 + m] = ctx[(size_t)(NTOT + n) * 8 + m]; }
    float hv[4];
#pragma unroll
    for (int c = 0; c < 4; c++) hv[c] = gru0[n * 4 + c];

    float zg[4], rr[4];
#pragma unroll
    for (int c = 0; c < 4; c++) {
        float az = sbz[c], ar = sbr[c];
#pragma unroll
        for (int q = 0; q < 18; q++) { az = fmaf(xin[q], sWz[c * 22 + q], az); ar = fmaf(xin[q], sWr[c * 22 + q], ar); }
#pragma unroll
        for (int q = 0; q < 4; q++) { az = fmaf(hv[q], sWz[c * 22 + 18 + q], az); ar = fmaf(hv[q], sWr[c * 22 + 18 + q], ar); }
        zg[c] = __fdividef(1.0f, 1.0f + __expf(-az));
        rr[c] = __fdividef(1.0f, 1.0f + __expf(-ar));
    }
    float ng[4];
#pragma unroll
    for (int c = 0; c < 4; c++) {
        float ah = sbh[c];
#pragma unroll
        for (int q = 0; q < 18; q++) ah = fmaf(xin[q], sWh[c * 22 + q], ah);
#pragma unroll
        for (int q = 0; q < 4; q++) ah = fmaf(rr[q] * hv[q], sWh[c * 22 + 18 + q], ah);
        float ht = tanhf(ah);
        ng[c] = fmaf(zg[c], ht - hv[c], hv[c]);
        out[NTOT + n * 4 + c] = ng[c];
    }

    float pin[22];
#pragma unroll
    for (int c = 0; c < 4; c++) pin[c] = ng[c];
#pragma unroll
    for (int m = 0; m < 16; m++) pin[4 + m] = xin[2 + m];
    pin[20] = gv; pin[21] = sv;

    float tot = 0.0f;
#pragma unroll
    for (int hd = 0; hd < 4; hd++) {
        float q[8];
#pragma unroll
        for (int m = 0; m < 8; m++) {
            float a = 0.0f;
#pragma unroll
            for (int qq = 0; qq < 22; qq++) a = fmaf(pin[qq], sqW[hd * 176 + m * 22 + qq], a);
            q[m] = a;
        }
        int ia = 0, ib = 0;
        float ba = -3.4e38f, bb = -3.4e38f;
#pragma unroll
        for (int p = 0; p < 12; p++) {
            float sa = q[0] * skA[hd * 48 + p * 4 + 0];
            sa = fmaf(q[1], skA[hd * 48 + p * 4 + 1], sa);
            sa = fmaf(q[2], skA[hd * 48 + p * 4 + 2], sa);
            sa = fmaf(q[3], skA[hd * 48 + p * 4 + 3], sa);
            if (sa > ba) { ba = sa; ia = p; }
            float sb = q[4] * skB[hd * 48 + p * 4 + 0];
            sb = fmaf(q[5], skB[hd * 48 + p * 4 + 1], sb);
            sb = fmaf(q[6], skB[hd * 48 + p * 4 + 2], sb);
            sb = fmaf(q[7], skB[hd * 48 + p * 4 + 3], sb);
            if (sb > bb) { bb = sb; ib = p; }
        }
        int e = ia * 12 + ib;
        float acc = seb2[e];
#pragma unroll
        for (int eh = 0; eh < 16; eh++) {
            float z1 = fmaf(seW1[e * 17 + eh], gv, seb1[e * 17 + eh]);
            z1 = fmaxf(z1, 0.0f);
            acc = fmaf(seW2[e * 17 + eh], z1, acc);
        }
        tot += acc;
    }
    out[n] = fmaf(0.1f * 0.25f, tot, gv);  // g + RESCALE * total/NH
}

// ---------------- launch ----------------
extern "C" void kernel_launch(void* const* d_in, const int* in_sizes, int n_in,
                              void* d_out, int out_size) {
    const float* grad      = (const float*)d_in[0];
    const float* sharp     = (const float*)d_in[1];
    const float* gru_state = (const float*)d_in[2];
    const float* mfwd      = (const float*)d_in[3];
    const float* mbwd      = (const float*)d_in[4];
    const float* inproj_W  = (const float*)d_in[5];
    const float* inproj_b  = (const float*)d_in[6];
    const float* m_inW     = (const float*)d_in[7];
    const float* m_dtW     = (const float*)d_in[8];
    const float* m_dtb     = (const float*)d_in[9];
    const float* m_BW      = (const float*)d_in[10];
    const float* m_CW      = (const float*)d_in[11];
    const float* m_Alog    = (const float*)d_in[12];
    const float* m_D       = (const float*)d_in[13];
    const float* m_rope    = (const float*)d_in[14];
    const float* m_outW    = (const float*)d_in[15];
    const float* gru_Wz    = (const float*)d_in[16];
    const float* gru_bz    = (const float*)d_in[17];
    const float* gru_Wr    = (const float*)d_in[18];
    const float* gru_br    = (const float*)d_in[19];
    const float* gru_Wh    = (const float*)d_in[20];
    const float* gru_bh    = (const float*)d_in[21];
    const float* peer_qW   = (const float*)d_in[22];
    const float* keysA     = (const float*)d_in[23];
    const float* keysB     = (const float*)d_in[24];
    const float* eW1       = (const float*)d_in[25];
    const float* eb1       = (const float*)d_in[26];
    const float* eW2       = (const float*)d_in[27];
    const float* eb2       = (const float*)d_in[28];
    float* out = (float*)d_out;

    unsigned int *ki, *ko, *vi, *vo;
    void* tmp;
    float *xbuf, *ysbuf, *ctxbuf;
    cudaGetSymbolAddress((void**)&ki, g_keys);
    cudaGetSymbolAddress((void**)&ko, g_keys2);
    cudaGetSymbolAddress((void**)&vi, g_idx);
    cudaGetSymbolAddress((void**)&vo, g_idx2);
    cudaGetSymbolAddress(&tmp, g_cubtemp);
    cudaGetSymbolAddress((void**)&xbuf, g_x);
    cudaGetSymbolAddress((void**)&ysbuf, g_ys);
    cudaGetSymbolAddress((void**)&ctxbuf, g_ctx);

    prep_kernel<<<NTOT / 256, 256>>>(grad, ki, vi);

    size_t temp_bytes = sizeof(g_cubtemp);
    cub::DeviceRadixSort::SortPairs(tmp, temp_bytes, ki, ko, vi, vo, NTOT, 0, 32,
                                    (cudaStream_t)0);

    xproj_kernel<<<NTOT / 256, 256>>>(grad, sharp, vo, inproj_W, inproj_b, xbuf);

    scan_kernel<<<dim3(NCH, 2), 256>>>(xbuf, m_inW, m_dtW, m_dtb, m_BW, m_CW,
                                       m_Alog, m_rope, mfwd, mbwd, ysbuf,
                                       out + 5 * NTOT);

    post_kernel<<<NTOT / 256, 256>>>(xbuf, ysbuf, vo, m_inW, m_D, m_outW, ctxbuf);

    gp_kernel<<<NTOT / 256, 256>>>(grad, sharp, gru_state, ctxbuf,
                                   gru_Wz, gru_bz, gru_Wr, gru_br, gru_Wh, gru_bh,
                                   peer_qW, keysA, keysB, eW1, eb1, eW2, eb2, out);

    (void)in_sizes; (void)n_in; (void)out_size;
}

// round 4
// speedup vs baseline: 1.2778x; 1.2778x over previous
#include <cuda_runtime.h>
#include <cuda_bf16.h>
#include <cub/cub.cuh>
#include <math.h>

#define NTOT 65536
#define L_CH 512
#define WARMUP 384
#define NCH (NTOT / L_CH)   // 128

// ---------------- static scratch (no allocations allowed) ----------------
__device__ unsigned int g_keys[NTOT];
__device__ unsigned int g_keys2[NTOT];
__device__ unsigned int g_idx[NTOT];
__device__ unsigned int g_idx2[NTOT];
__device__ unsigned char g_cubtemp[1 << 23];   // 8 MB, plenty for 64K pairs
__device__ float g_x[NTOT * 8];                // sorted-order features
__device__ float g_ys[2 * NTOT * 16];          // raw scan outputs (dir, sortedpos, i)
__device__ float g_ctx[2 * NTOT * 8];          // fwd/bwd ctx in ORIGINAL order

// ---------------- kernel 1: sort keys ----------------
__global__ void prep_kernel(const float* __restrict__ g,
                            unsigned int* __restrict__ keys,
                            unsigned int* __restrict__ vals) {
    int n = blockIdx.x * blockDim.x + threadIdx.x;
    keys[n] = __float_as_uint(g[n]) & 0x7fffffffu;  // |g| bits sort as uint
    vals[n] = (unsigned)n;
}

// ---------------- kernel 2: x = [gs, ss] @ inproj_W.T + b (sorted order) ----------------
__global__ void xproj_kernel(const float* __restrict__ g, const float* __restrict__ s,
                             const unsigned int* __restrict__ sidx,
                             const float* __restrict__ W, const float* __restrict__ b,
                             float* __restrict__ x) {
    int k = blockIdx.x * blockDim.x + threadIdx.x;
    int o = sidx[k];
    float gv = g[o], sv = s[o];
#pragma unroll
    for (int m = 0; m < 8; m++)
        x[k * 8 + m] = fmaf(gv, W[m * 2 + 0], fmaf(sv, W[m * 2 + 1], b[m]));
}

// ---------------- kernel 3: chunked warmup Mamba scan (both directions) ----------------
// Restructure: per 16-step tile
//   A) parallel projections (xb, dt, B, C) using 256 threads as (t,c)
//   B) per-thread (i,j) precompute of recurrence coefficients ca/cb/db for
//      all 16 steps (h-independent -> off the dependent chain)
//   C) tight recurrence: shfl + 2 FMA (+ STS h when producing output)
//   D) parallel y = sum_j h*C from shared (output tiles only)
__global__ void __launch_bounds__(256) scan_kernel(
    const float* __restrict__ x,
    const float* __restrict__ inW,   // (2,32,8)
    const float* __restrict__ dtW,   // (2,16,16)
    const float* __restrict__ dtb,   // (2,16)
    const float* __restrict__ BW,    // (2,16,16)
    const float* __restrict__ CW,    // (2,16,16)
    const float* __restrict__ Alog,  // (2,16,16)
    const float* __restrict__ rope,  // (2,16,16)
    const float* __restrict__ h0f, const float* __restrict__ h0b,
    float* __restrict__ ys,          // (2,N,16)
    float* __restrict__ hfin)        // 512 floats: new_fwd then new_bwd
{
    const int dir = blockIdx.y;
    const int chunk = blockIdx.x;
    const int tid = threadIdx.x;
    const int i = tid >> 4, j = tid & 15;
    const int lane = tid & 31;
    const int srcRot = (lane & 16) | ((lane + 15) & 15);  // j-1 mod 16 within 16-lane group

    __shared__ float s_inWx[8][16];   // [m][i]
    __shared__ float s_dtWT[16][16];  // [k][i]
    __shared__ float s_BWT[16][16];   // [k][j]
    __shared__ float s_CWT[16][16];
    __shared__ float s_dtb[16];
    __shared__ float sx[16][8];
    __shared__ float sxb[16][16];
    __shared__ float sdt[16][16];
    __shared__ float sdxb[16][16];
    __shared__ float sB[16][16];
    __shared__ float sC[16][16];
    __shared__ float sh[16][16][17];  // padded: conflict-free write(t,i,j) & read(j-loop)

    if (tid < 128) { int m = tid >> 4, c = tid & 15; s_inWx[m][c] = inW[dir * 256 + c * 8 + m]; }
    { int k = tid >> 4, c = tid & 15;
      s_dtWT[k][c] = dtW[dir * 256 + c * 16 + k];
      s_BWT[k][c]  = BW [dir * 256 + c * 16 + k];
      s_CWT[k][c]  = CW [dir * 256 + c * 16 + k]; }
    if (tid < 16) s_dtb[tid] = dtb[dir * 16 + tid];

    const float Ac = -__expf(Alog[dir * 256 + tid]);
    const float Rc = rope[dir * 256 + tid];

    int g0 = chunk * L_CH - WARMUP;
    float h;
    if (g0 <= 0) { g0 = 0; h = (dir == 0 ? h0f : h0b)[tid]; }  // exact initial state
    else h = 0.0f;                                             // warmup (state decays)
    const int gend = (chunk + 1) * L_CH;
    const int outStart = chunk * L_CH;

    __syncthreads();

    for (int base = g0; base < gend; base += 16) {
        const bool doOut = (base >= outStart);   // block-uniform
        if (tid < 128) {  // stage inputs
            int t = tid >> 3, m = tid & 7;
            int p = (dir == 0) ? (base + t) : (NTOT - 1 - (base + t));
            sx[t][m] = x[p * 8 + m];
        }
        __syncthreads();
        {   // xb projection
            int t = tid >> 4, c = tid & 15;
            float acc = 0.0f;
#pragma unroll
            for (int m = 0; m < 8; m++) acc = fmaf(sx[t][m], s_inWx[m][c], acc);
            sxb[t][c] = acc;
        }
        __syncthreads();
        {   // dt / B (+C for output tiles) projections
            int t = tid >> 4, c = tid & 15;
            float u = s_dtb[c], bv = 0.0f;
#pragma unroll
            for (int k = 0; k < 16; k++) {
                float xbk = sxb[t][k];
                u  = fmaf(xbk, s_dtWT[k][c], u);
                bv = fmaf(xbk, s_BWT[k][c], bv);
            }
            float dt = (u > 15.0f) ? u : log1pf(__expf(u));  // softplus
            sdt[t][c] = dt;
            sdxb[t][c] = dt * sxb[t][c];
            sB[t][c] = bv;
            if (doOut) {
                float cv = 0.0f;
#pragma unroll
                for (int k = 0; k < 16; k++) cv = fmaf(sxb[t][k], s_CWT[k][c], cv);
                sC[t][c] = cv;
            }
        }
        __syncthreads();
        // ---- phase B: per-(i,j) coefficient precompute (no h dependence) ----
        float ca[16], cb[16], db[16];
#pragma unroll
        for (int t = 0; t < 16; t++) {
            float dt = sdt[t][i];
            float ph = dt * Rc;
            float p2 = ph * ph;
            // |ph| <= ~0.2: 3-term Taylor is < 1e-8 abs error
            float sn = ph * fmaf(p2, fmaf(p2, 1.0f / 120.0f, -1.0f / 6.0f), 1.0f);
            float cs = fmaf(p2, fmaf(p2, 1.0f / 24.0f, -0.5f), 1.0f);
            float xA  = dt * Ac;
            float num = fmaf(0.5f, xA, 1.0f);
            float den = fmaf(-0.5f, xA, 1.0f + 1e-8f);
            float t_r = num * __frcp_rn(den);
            ca[t] = cs * t_r;
            cb[t] = sn * t_r;
            db[t] = sdxb[t][i] * sB[t][j];
        }
        // ---- phase C: tight recurrence ----
        if (doOut) {
#pragma unroll
            for (int t = 0; t < 16; t++) {
                float hm1 = __shfl_sync(0xffffffffu, h, srcRot);
                h = fmaf(ca[t], h, fmaf(-cb[t], hm1, db[t]));
                sh[t][i][j] = h;
            }
            __syncthreads();
            // ---- phase D: y = sum_j h*C, fully parallel ----
            int t = tid >> 4, ii = tid & 15;
            float acc = 0.0f;
#pragma unroll
            for (int jj = 0; jj < 16; jj++)
                acc = fmaf(sh[t][ii][jj], sC[t][jj], acc);
            int p = (dir == 0) ? (base + t) : (NTOT - 1 - (base + t));
            ys[((size_t)dir * NTOT + p) * 16 + ii] = acc;
            // no trailing sync needed: next tile's first __syncthreads orders
            // these reads before any re-write of sh/sC.
        } else {
#pragma unroll
            for (int t = 0; t < 16; t++) {
                float hm1 = __shfl_sync(0xffffffffu, h, srcRot);
                h = fmaf(ca[t], h, fmaf(-cb[t], hm1, db[t]));
            }
        }
        __syncthreads();
    }
    if (chunk == NCH - 1) hfin[dir * 256 + tid] = h;  // final states (outputs)
}

// ---------------- kernel 4: epilogue projections + scatter to original order ----------------
__global__ void post_kernel(const float* __restrict__ x, const float* __restrict__ ys,
                            const unsigned int* __restrict__ sidx,
                            const float* __restrict__ inW, const float* __restrict__ D,
                            const float* __restrict__ outW, float* __restrict__ ctx) {
    int k = blockIdx.x * blockDim.x + threadIdx.x;
    float4 xv0 = ((const float4*)x)[k * 2 + 0];
    float4 xv1 = ((const float4*)x)[k * 2 + 1];
    float xv[8] = {xv0.x, xv0.y, xv0.z, xv0.w, xv1.x, xv1.y, xv1.z, xv1.w};
    int o = sidx[k];
#pragma unroll
    for (int d = 0; d < 2; d++) {
        float yv[16];
#pragma unroll
        for (int q = 0; q < 4; q++) {
            float4 y4 = ((const float4*)ys)[((size_t)d * NTOT + k) * 4 + q];
            yv[q * 4 + 0] = y4.x; yv[q * 4 + 1] = y4.y;
            yv[q * 4 + 2] = y4.z; yv[q * 4 + 3] = y4.w;
        }
        float out[8];
#pragma unroll
        for (int m = 0; m < 8; m++) out[m] = 0.0f;
#pragma unroll
        for (int ii = 0; ii < 16; ii++) {
            float xb = 0.0f, z = 0.0f;
#pragma unroll
            for (int m = 0; m < 8; m++) {
                xb = fmaf(xv[m], inW[d * 256 + ii * 8 + m], xb);
                z  = fmaf(xv[m], inW[d * 256 + (16 + ii) * 8 + m], z);
            }
            float sg = __fdividef(1.0f, 1.0f + __expf(-z));
            float yi = fmaf(yv[ii], z * sg, D[d * 16 + ii] * xb);
#pragma unroll
            for (int m = 0; m < 8; m++)
                out[m] = fmaf(yi, outW[d * 128 + m * 16 + ii], out[m]);
        }
        float4* cbase = (float4*)&ctx[((size_t)d * NTOT + o) * 8];
        cbase[0] = make_float4(out[0], out[1], out[2], out[3]);
        cbase[1] = make_float4(out[4], out[5], out[6], out[7]);
    }
}

// ---------------- kernel 5: GRU + PEER routing/experts + final combine ----------------
__global__ void __launch_bounds__(256) gp_kernel(
    const float* __restrict__ g, const float* __restrict__ s,
    const float* __restrict__ gru0, const float* __restrict__ ctx,
    const float* __restrict__ Wz, const float* __restrict__ bz,
    const float* __restrict__ Wr, const float* __restrict__ br,
    const float* __restrict__ Wh, const float* __restrict__ bh,
    const float* __restrict__ qW, const float* __restrict__ kA, const float* __restrict__ kB,
    const float* __restrict__ eW1, const float* __restrict__ eb1,
    const float* __restrict__ eW2, const float* __restrict__ eb2,
    float* __restrict__ out) {
    __shared__ float sWz[88], sWr[88], sWh[88], sbz[4], sbr[4], sbh[4];
    __shared__ float sqW[704];       // (4,8,22)
    __shared__ float skA[192], skB[192];
    __shared__ float seW1[144 * 17], seb1[144 * 17], seW2[144 * 17];  // pad vs bank conflicts
    __shared__ float seb2[144];

    int tid = threadIdx.x;
    for (int q = tid; q < 88; q += 256) { sWz[q] = Wz[q]; sWr[q] = Wr[q]; sWh[q] = Wh[q]; }
    if (tid < 4) { sbz[tid] = bz[tid]; sbr[tid] = br[tid]; sbh[tid] = bh[tid]; }
    for (int q = tid; q < 704; q += 256) sqW[q] = qW[q];
    for (int q = tid; q < 192; q += 256) { skA[q] = kA[q]; skB[q] = kB[q]; }
    for (int q = tid; q < 2304; q += 256) {
        int e = q >> 4, eh = q & 15;
        seW1[e * 17 + eh] = eW1[q];
        seb1[e * 17 + eh] = eb1[q];
        seW2[e * 17 + eh] = eW2[q];
    }
    for (int q = tid; q < 144; q += 256) seb2[q] = eb2[q];
    __syncthreads();

    int n = blockIdx.x * blockDim.x + tid;
    float gv = g[n], sv = s[n];
    float xin[18];
    xin[0] = gv; xin[1] = sv;
#pragma unroll
    for (int m = 0; m < 8; m++) { xin[2 + m] = ctx[(size_t)n * 8 + m]; xin[10 + m] = ctx[(size_t)(NTOT + n) * 8 + m]; }
    float hv[4];
#pragma unroll
    for (int c = 0; c < 4; c++) hv[c] = gru0[n * 4 + c];

    float zg[4], rr[4];
#pragma unroll
    for (int c = 0; c < 4; c++) {
        float az = sbz[c], ar = sbr[c];
#pragma unroll
        for (int q = 0; q < 18; q++) { az = fmaf(xin[q], sWz[c * 22 + q], az); ar = fmaf(xin[q], sWr[c * 22 + q], ar); }
#pragma unroll
        for (int q = 0; q < 4; q++) { az = fmaf(hv[q], sWz[c * 22 + 18 + q], az); ar = fmaf(hv[q], sWr[c * 22 + 18 + q], ar); }
        zg[c] = __fdividef(1.0f, 1.0f + __expf(-az));
        rr[c] = __fdividef(1.0f, 1.0f + __expf(-ar));
    }
    float ng[4];
#pragma unroll
    for (int c = 0; c < 4; c++) {
        float ah = sbh[c];
#pragma unroll
        for (int q = 0; q < 18; q++) ah = fmaf(xin[q], sWh[c * 22 + q], ah);
#pragma unroll
        for (int q = 0; q < 4; q++) ah = fmaf(rr[q] * hv[q], sWh[c * 22 + 18 + q], ah);
        float ht = tanhf(ah);
        ng[c] = fmaf(zg[c], ht - hv[c], hv[c]);
        out[NTOT + n * 4 + c] = ng[c];
    }

    float pin[22];
#pragma unroll
    for (int c = 0; c < 4; c++) pin[c] = ng[c];
#pragma unroll
    for (int m = 0; m < 16; m++) pin[4 + m] = xin[2 + m];
    pin[20] = gv; pin[21] = sv;

    float tot = 0.0f;
#pragma unroll
    for (int hd = 0; hd < 4; hd++) {
        float q[8];
#pragma unroll
        for (int m = 0; m < 8; m++) {
            float a = 0.0f;
#pragma unroll
            for (int qq = 0; qq < 22; qq++) a = fmaf(pin[qq], sqW[hd * 176 + m * 22 + qq], a);
            q[m] = a;
        }
        int ia = 0, ib = 0;
        float ba = -3.4e38f, bb = -3.4e38f;
#pragma unroll
        for (int p = 0; p < 12; p++) {
            float sa = q[0] * skA[hd * 48 + p * 4 + 0];
            sa = fmaf(q[1], skA[hd * 48 + p * 4 + 1], sa);
            sa = fmaf(q[2], skA[hd * 48 + p * 4 + 2], sa);
            sa = fmaf(q[3], skA[hd * 48 + p * 4 + 3], sa);
            if (sa > ba) { ba = sa; ia = p; }
            float sb = q[4] * skB[hd * 48 + p * 4 + 0];
            sb = fmaf(q[5], skB[hd * 48 + p * 4 + 1], sb);
            sb = fmaf(q[6], skB[hd * 48 + p * 4 + 2], sb);
            sb = fmaf(q[7], skB[hd * 48 + p * 4 + 3], sb);
            if (sb > bb) { bb = sb; ib = p; }
        }
        int e = ia * 12 + ib;
        float acc = seb2[e];
#pragma unroll
        for (int eh = 0; eh < 16; eh++) {
            float z1 = fmaf(seW1[e * 17 + eh], gv, seb1[e * 17 + eh]);
            z1 = fmaxf(z1, 0.0f);
            acc = fmaf(seW2[e * 17 + eh], z1, acc);
        }
        tot += acc;
    }
    out[n] = fmaf(0.1f * 0.25f, tot, gv);  // g + RESCALE * total/NH
}

// ---------------- launch ----------------
extern "C" void kernel_launch(void* const* d_in, const int* in_sizes, int n_in,
                              void* d_out, int out_size) {
    const float* grad      = (const float*)d_in[0];
    const float* sharp     = (const float*)d_in[1];
    const float* gru_state = (const float*)d_in[2];
    const float* mfwd      = (const float*)d_in[3];
    const float* mbwd      = (const float*)d_in[4];
    const float* inproj_W  = (const float*)d_in[5];
    const float* inproj_b  = (const float*)d_in[6];
    const float* m_inW     = (const float*)d_in[7];
    const float* m_dtW     = (const float*)d_in[8];
    const float* m_dtb     = (const float*)d_in[9];
    const float* m_BW      = (const float*)d_in[10];
    const float* m_CW      = (const float*)d_in[11];
    const float* m_Alog    = (const float*)d_in[12];
    const float* m_D       = (const float*)d_in[13];
    const float* m_rope    = (const float*)d_in[14];
    const float* m_outW    = (const float*)d_in[15];
    const float* gru_Wz    = (const float*)d_in[16];
    const float* gru_bz    = (const float*)d_in[17];
    const float* gru_Wr    = (const float*)d_in[18];
    const float* gru_br    = (const float*)d_in[19];
    const float* gru_Wh    = (const float*)d_in[20];
    const float* gru_bh    = (const float*)d_in[21];
    const float* peer_qW   = (const float*)d_in[22];
    const float* keysA     = (const float*)d_in[23];
    const float* keysB     = (const float*)d_in[24];
    const float* eW1       = (const float*)d_in[25];
    const float* eb1       = (const float*)d_in[26];
    const float* eW2       = (const float*)d_in[27];
    const float* eb2       = (const float*)d_in[28];
    float* out = (float*)d_out;

    unsigned int *ki, *ko, *vi, *vo;
    void* tmp;
    float *xbuf, *ysbuf, *ctxbuf;
    cudaGetSymbolAddress((void**)&ki, g_keys);
    cudaGetSymbolAddress((void**)&ko, g_keys2);
    cudaGetSymbolAddress((void**)&vi, g_idx);
    cudaGetSymbolAddress((void**)&vo, g_idx2);
    cudaGetSymbolAddress(&tmp, g_cubtemp);
    cudaGetSymbolAddress((void**)&xbuf, g_x);
    cudaGetSymbolAddress((void**)&ysbuf, g_ys);
    cudaGetSymbolAddress((void**)&ctxbuf, g_ctx);

    prep_kernel<<<NTOT / 256, 256>>>(grad, ki, vi);

    size_t temp_bytes = sizeof(g_cubtemp);
    cub::DeviceRadixSort::SortPairs(tmp, temp_bytes, ki, ko, vi, vo, NTOT, 0, 32,
                                    (cudaStream_t)0);

    xproj_kernel<<<NTOT / 256, 256>>>(grad, sharp, vo, inproj_W, inproj_b, xbuf);

    scan_kernel<<<dim3(NCH, 2), 256>>>(xbuf, m_inW, m_dtW, m_dtb, m_BW, m_CW,
                                       m_Alog, m_rope, mfwd, mbwd, ysbuf,
                                       out + 5 * NTOT);

    post_kernel<<<NTOT / 256, 256>>>(xbuf, ysbuf, vo, m_inW, m_D, m_outW, ctxbuf);

    gp_kernel<<<NTOT / 256, 256>>>(grad, sharp, gru_state, ctxbuf,
                                   gru_Wz, gru_bz, gru_Wr, gru_br, gru_Wh, gru_bh,
                                   peer_qW, keysA, keysB, eW1, eb1, eW2, eb2, out);

    (void)in_sizes; (void)n_in; (void)out_size;
}

// round 6
// speedup vs baseline: 1.4724x; 1.1523x over previous
#include <cuda_runtime.h>
#include <cuda_bf16.h>
#include <cub/cub.cuh>
#include <math.h>

#define NTOT 65536
#define L_CH 256
#define WARMUP 128
#define NCH (NTOT / L_CH)   // 256

// ---------------- static scratch (no allocations allowed) ----------------
__device__ unsigned int g_keys[NTOT];
__device__ unsigned int g_keys2[NTOT];
__device__ unsigned int g_idx[NTOT];
__device__ unsigned int g_idx2[NTOT];
__device__ unsigned char g_cubtemp[1 << 23];   // 8 MB, plenty for 64K pairs
__device__ float g_x[NTOT * 8];                // sorted-order features
__device__ float g_ys[2 * NTOT * 16];          // raw scan outputs (dir, sortedpos, i)
__device__ float g_ctx[2 * NTOT * 8];          // fwd/bwd ctx in ORIGINAL order

// ---------------- kernel 1: sort keys ----------------
__global__ void prep_kernel(const float* __restrict__ g,
                            unsigned int* __restrict__ keys,
                            unsigned int* __restrict__ vals) {
    int n = blockIdx.x * blockDim.x + threadIdx.x;
    keys[n] = __float_as_uint(g[n]) & 0x7fffffffu;  // |g| bits sort as uint
    vals[n] = (unsigned)n;
}

// ---------------- kernel 2: x = [gs, ss] @ inproj_W.T + b (sorted order) ----------------
__global__ void xproj_kernel(const float* __restrict__ g, const float* __restrict__ s,
                             const unsigned int* __restrict__ sidx,
                             const float* __restrict__ W, const float* __restrict__ b,
                             float* __restrict__ x) {
    int k = blockIdx.x * blockDim.x + threadIdx.x;
    int o = sidx[k];
    float gv = g[o], sv = s[o];
#pragma unroll
    for (int m = 0; m < 8; m++)
        x[k * 8 + m] = fmaf(gv, W[m * 2 + 0], fmaf(sv, W[m * 2 + 1], b[m]));
}

// ---------------- kernel 3: chunked warmup Mamba scan (both directions) ----------------
// Per 16-step tile:
//   A) parallel projections (xb, dt, B[, C]) with 256 threads as (t,c)
//   B) per-(i,j) precompute of ca/cb/db for 16 steps (off the dependent chain)
//   C) tight recurrence: shfl + 2 FMA (+ STS h when producing output)
//   D) parallel y = sum_j h*C from shared (output tiles only)
// x for the NEXT tile is prefetched into registers during B/C to hide L2 latency.
__global__ void __launch_bounds__(256) scan_kernel(
    const float* __restrict__ x,
    const float* __restrict__ inW,   // (2,32,8)
    const float* __restrict__ dtW,   // (2,16,16)
    const float* __restrict__ dtb,   // (2,16)
    const float* __restrict__ BW,    // (2,16,16)
    const float* __restrict__ CW,    // (2,16,16)
    const float* __restrict__ Alog,  // (2,16,16)
    const float* __restrict__ rope,  // (2,16,16)
    const float* __restrict__ h0f, const float* __restrict__ h0b,
    float* __restrict__ ys,          // (2,N,16)
    float* __restrict__ hfin)        // 512 floats: new_fwd then new_bwd
{
    const int dir = blockIdx.y;
    const int chunk = blockIdx.x;
    const int tid = threadIdx.x;
    const int i = tid >> 4, j = tid & 15;
    const int lane = tid & 31;
    const int srcRot = (lane & 16) | ((lane + 15) & 15);  // j-1 mod 16 within 16-lane group

    __shared__ float s_inWx[8][16];   // [m][i]
    __shared__ float s_dtWT[16][16];  // [k][i]
    __shared__ float s_BWT[16][16];   // [k][j]
    __shared__ float s_CWT[16][16];
    __shared__ float s_dtb[16];
    __shared__ float sx[16][8];
    __shared__ float sxb[16][16];
    __shared__ float sdt[16][16];
    __shared__ float sdxb[16][16];
    __shared__ float sB[16][16];
    __shared__ float sC[16][16];
    __shared__ float sh[16][16][17];  // padded: conflict-free write(t,i,j) & read(j-loop)

    if (tid < 128) { int m = tid >> 4, c = tid & 15; s_inWx[m][c] = inW[dir * 256 + c * 8 + m]; }
    { int k = tid >> 4, c = tid & 15;
      s_dtWT[k][c] = dtW[dir * 256 + c * 16 + k];
      s_BWT[k][c]  = BW [dir * 256 + c * 16 + k];
      s_CWT[k][c]  = CW [dir * 256 + c * 16 + k]; }
    if (tid < 16) s_dtb[tid] = dtb[dir * 16 + tid];

    const float Ac = -__expf(Alog[dir * 256 + tid]);
    const float Rc = rope[dir * 256 + tid];

    int g0 = chunk * L_CH - WARMUP;
    float h;
    if (g0 <= 0) { g0 = 0; h = (dir == 0 ? h0f : h0b)[tid]; }  // exact initial state
    else h = 0.0f;                                             // warmup (state decays)
    const int gend = (chunk + 1) * L_CH;
    const int outStart = chunk * L_CH;

    const int xt = tid >> 3, xm = tid & 7;   // staging role for tid<128
    float xr = 0.0f;
    if (tid < 128) {
        int p = (dir == 0) ? (g0 + xt) : (NTOT - 1 - (g0 + xt));
        xr = x[p * 8 + xm];
    }
    __syncthreads();

    for (int base = g0; base < gend; base += 16) {
        const bool doOut = (base >= outStart);   // block-uniform
        if (tid < 128) sx[xt][xm] = xr;
        __syncthreads();                                         // S1
        {   // xb projection
            int t = tid >> 4, c = tid & 15;
            float acc = 0.0f;
#pragma unroll
            for (int m = 0; m < 8; m++) acc = fmaf(sx[t][m], s_inWx[m][c], acc);
            sxb[t][c] = acc;
        }
        __syncthreads();                                         // S2
        {   // dt / B (+C for output tiles) projections
            int t = tid >> 4, c = tid & 15;
            float u = s_dtb[c], bv = 0.0f;
#pragma unroll
            for (int k = 0; k < 16; k++) {
                float xbk = sxb[t][k];
                u  = fmaf(xbk, s_dtWT[k][c], u);
                bv = fmaf(xbk, s_BWT[k][c], bv);
            }
            float dt = (u > 15.0f) ? u : log1pf(__expf(u));  // softplus
            sdt[t][c] = dt;
            sdxb[t][c] = dt * sxb[t][c];
            sB[t][c] = bv;
            if (doOut) {
                float cv = 0.0f;
#pragma unroll
                for (int k = 0; k < 16; k++) cv = fmaf(sxb[t][k], s_CWT[k][c], cv);
                sC[t][c] = cv;
            }
        }
        // prefetch next tile's x (latency hidden behind phases B/C/D)
        if (tid < 128 && base + 16 < gend) {
            int p = (dir == 0) ? (base + 16 + xt) : (NTOT - 1 - (base + 16 + xt));
            xr = x[p * 8 + xm];
        }
        __syncthreads();                                         // S3
        // ---- phase B: per-(i,j) coefficient precompute (no h dependence) ----
        float ca[16], cb[16], db[16];
#pragma unroll
        for (int t = 0; t < 16; t++) {
            float dt = sdt[t][i];
            float ph = dt * Rc;
            float p2 = ph * ph;
            // |ph| <= ~0.2: 3-term Taylor is < 1e-8 abs error
            float sn = ph * fmaf(p2, fmaf(p2, 1.0f / 120.0f, -1.0f / 6.0f), 1.0f);
            float cs = fmaf(p2, fmaf(p2, 1.0f / 24.0f, -0.5f), 1.0f);
            float xA  = dt * Ac;
            float num = fmaf(0.5f, xA, 1.0f);
            float den = fmaf(-0.5f, xA, 1.0f + 1e-8f);
            float t_r = num * __frcp_rn(den);
            ca[t] = cs * t_r;
            cb[t] = sn * t_r;
            db[t] = sdxb[t][i] * sB[t][j];
        }
        // ---- phase C: tight recurrence ----
        if (doOut) {
#pragma unroll
            for (int t = 0; t < 16; t++) {
                float hm1 = __shfl_sync(0xffffffffu, h, srcRot);
                h = fmaf(ca[t], h, fmaf(-cb[t], hm1, db[t]));
                sh[t][i][j] = h;
            }
            __syncthreads();                                     // S4
            // ---- phase D: y = sum_j h*C, fully parallel ----
            int t = tid >> 4, ii = tid & 15;
            float acc = 0.0f;
#pragma unroll
            for (int jj = 0; jj < 16; jj++)
                acc = fmaf(sh[t][ii][jj], sC[t][jj], acc);
            int p = (dir == 0) ? (base + t) : (NTOT - 1 - (base + t));
            ys[((size_t)dir * NTOT + p) * 16 + ii] = acc;
        } else {
#pragma unroll
            for (int t = 0; t < 16; t++) {
                float hm1 = __shfl_sync(0xffffffffu, h, srcRot);
                h = fmaf(ca[t], h, fmaf(-cb[t], hm1, db[t]));
            }
        }
        // no trailing sync: next tile's S1 orders all cross-tile hazards
        // (every smem buffer is re-written only after a later barrier that
        //  all readers have already passed).
    }
    if (chunk == NCH - 1) hfin[dir * 256 + tid] = h;  // final states (outputs)
}

// ---------------- kernel 4: epilogue projections + scatter to original order ----------------
__global__ void post_kernel(const float* __restrict__ x, const float* __restrict__ ys,
                            const unsigned int* __restrict__ sidx,
                            const float* __restrict__ inW, const float* __restrict__ D,
                            const float* __restrict__ outW, float* __restrict__ ctx) {
    int k = blockIdx.x * blockDim.x + threadIdx.x;
    float4 xv0 = ((const float4*)x)[k * 2 + 0];
    float4 xv1 = ((const float4*)x)[k * 2 + 1];
    float xv[8] = {xv0.x, xv0.y, xv0.z, xv0.w, xv1.x, xv1.y, xv1.z, xv1.w};
    int o = sidx[k];
#pragma unroll
    for (int d = 0; d < 2; d++) {
        float yv[16];
#pragma unroll
        for (int q = 0; q < 4; q++) {
            float4 y4 = ((const float4*)ys)[((size_t)d * NTOT + k) * 4 + q];
            yv[q * 4 + 0] = y4.x; yv[q * 4 + 1] = y4.y;
            yv[q * 4 + 2] = y4.z; yv[q * 4 + 3] = y4.w;
        }
        float out[8];
#pragma unroll
        for (int m = 0; m < 8; m++) out[m] = 0.0f;
#pragma unroll
        for (int ii = 0; ii < 16; ii++) {
            float xb = 0.0f, z = 0.0f;
#pragma unroll
            for (int m = 0; m < 8; m++) {
                xb = fmaf(xv[m], inW[d * 256 + ii * 8 + m], xb);
                z  = fmaf(xv[m], inW[d * 256 + (16 + ii) * 8 + m], z);
            }
            float sg = __fdividef(1.0f, 1.0f + __expf(-z));
            float yi = fmaf(yv[ii], z * sg, D[d * 16 + ii] * xb);
#pragma unroll
            for (int m = 0; m < 8; m++)
                out[m] = fmaf(yi, outW[d * 128 + m * 16 + ii], out[m]);
        }
        float4* cbase = (float4*)&ctx[((size_t)d * NTOT + o) * 8];
        cbase[0] = make_float4(out[0], out[1], out[2], out[3]);
        cbase[1] = make_float4(out[4], out[5], out[6], out[7]);
    }
}

// ---------------- kernel 5: GRU + PEER routing/experts + final combine ----------------
__global__ void __launch_bounds__(256) gp_kernel(
    const float* __restrict__ g, const float* __restrict__ s,
    const float* __restrict__ gru0, const float* __restrict__ ctx,
    const float* __restrict__ Wz, const float* __restrict__ bz,
    const float* __restrict__ Wr, const float* __restrict__ br,
    const float* __restrict__ Wh, const float* __restrict__ bh,
    const float* __restrict__ qW, const float* __restrict__ kA, const float* __restrict__ kB,
    const float* __restrict__ eW1, const float* __restrict__ eb1,
    const float* __restrict__ eW2, const float* __restrict__ eb2,
    float* __restrict__ out) {
    __shared__ float sWz[88], sWr[88], sWh[88], sbz[4], sbr[4], sbh[4];
    __shared__ float sqW[704];       // (4,8,22)
    __shared__ float skA[192], skB[192];
    __shared__ float seW1[144 * 17], seb1[144 * 17], seW2[144 * 17];  // pad vs bank conflicts
    __shared__ float seb2[144];

    int tid = threadIdx.x;
    for (int q = tid; q < 88; q += 256) { sWz[q] = Wz[q]; sWr[q] = Wr[q]; sWh[q] = Wh[q]; }
    if (tid < 4) { sbz[tid] = bz[tid]; sbr[tid] = br[tid]; sbh[tid] = bh[tid]; }
    for (int q = tid; q < 704; q += 256) sqW[q] = qW[q];
    for (int q = tid; q < 192; q += 256) { skA[q] = kA[q]; skB[q] = kB[q]; }
    for (int q = tid; q < 2304; q += 256) {
        int e = q >> 4, eh = q & 15;
        seW1[e * 17 + eh] = eW1[q];
        seb1[e * 17 + eh] = eb1[q];
        seW2[e * 17 + eh] = eW2[q];
    }
    for (int q = tid; q < 144; q += 256) seb2[q] = eb2[q];
    __syncthreads();

    int n = blockIdx.x * blockDim.x + tid;
    float gv = g[n], sv = s[n];
    float xin[18];
    xin[0] = gv; xin[1] = sv;
#pragma unroll
    for (int m = 0; m < 8; m++) { xin[2 + m] = ctx[(size_t)n * 8 + m]; xin[10 + m] = ctx[(size_t)(NTOT + n) * 8 + m]; }
    float hv[4];
#pragma unroll
    for (int c = 0; c < 4; c++) hv[c] = gru0[n * 4 + c];

    float zg[4], rr[4];
#pragma unroll
    for (int c = 0; c < 4; c++) {
        float az = sbz[c], ar = sbr[c];
#pragma unroll
        for (int q = 0; q < 18; q++) { az = fmaf(xin[q], sWz[c * 22 + q], az); ar = fmaf(xin[q], sWr[c * 22 + q], ar); }
#pragma unroll
        for (int q = 0; q < 4; q++) { az = fmaf(hv[q], sWz[c * 22 + 18 + q], az); ar = fmaf(hv[q], sWr[c * 22 + 18 + q], ar); }
        zg[c] = __fdividef(1.0f, 1.0f + __expf(-az));
        rr[c] = __fdividef(1.0f, 1.0f + __expf(-ar));
    }
    float ng[4];
#pragma unroll
    for (int c = 0; c < 4; c++) {
        float ah = sbh[c];
#pragma unroll
        for (int q = 0; q < 18; q++) ah = fmaf(xin[q], sWh[c * 22 + q], ah);
#pragma unroll
        for (int q = 0; q < 4; q++) ah = fmaf(rr[q] * hv[q], sWh[c * 22 + 18 + q], ah);
        float ht = tanhf(ah);
        ng[c] = fmaf(zg[c], ht - hv[c], hv[c]);
        out[NTOT + n * 4 + c] = ng[c];
    }

    float pin[22];
#pragma unroll
    for (int c = 0; c < 4; c++) pin[c] = ng[c];
#pragma unroll
    for (int m = 0; m < 16; m++) pin[4 + m] = xin[2 + m];
    pin[20] = gv; pin[21] = sv;

    float tot = 0.0f;
#pragma unroll
    for (int hd = 0; hd < 4; hd++) {
        float q[8];
#pragma unroll
        for (int m = 0; m < 8; m++) {
            float a = 0.0f;
#pragma unroll
            for (int qq = 0; qq < 22; qq++) a = fmaf(pin[qq], sqW[hd * 176 + m * 22 + qq], a);
            q[m] = a;
        }
        int ia = 0, ib = 0;
        float ba = -3.4e38f, bb = -3.4e38f;
#pragma unroll
        for (int p = 0; p < 12; p++) {
            float sa = q[0] * skA[hd * 48 + p * 4 + 0];
            sa = fmaf(q[1], skA[hd * 48 + p * 4 + 1], sa);
            sa = fmaf(q[2], skA[hd * 48 + p * 4 + 2], sa);
            sa = fmaf(q[3], skA[hd * 48 + p * 4 + 3], sa);
            if (sa > ba) { ba = sa; ia = p; }
            float sb = q[4] * skB[hd * 48 + p * 4 + 0];
            sb = fmaf(q[5], skB[hd * 48 + p * 4 + 1], sb);
            sb = fmaf(q[6], skB[hd * 48 + p * 4 + 2], sb);
            sb = fmaf(q[7], skB[hd * 48 + p * 4 + 3], sb);
            if (sb > bb) { bb = sb; ib = p; }
        }
        int e = ia * 12 + ib;
        float acc = seb2[e];
#pragma unroll
        for (int eh = 0; eh < 16; eh++) {
            float z1 = fmaf(seW1[e * 17 + eh], gv, seb1[e * 17 + eh]);
            z1 = fmaxf(z1, 0.0f);
            acc = fmaf(seW2[e * 17 + eh], z1, acc);
        }
        tot += acc;
    }
    out[n] = fmaf(0.1f * 0.25f, tot, gv);  // g + RESCALE * total/NH
}

// ---------------- launch ----------------
extern "C" void kernel_launch(void* const* d_in, const int* in_sizes, int n_in,
                              void* d_out, int out_size) {
    const float* grad      = (const float*)d_in[0];
    const float* sharp     = (const float*)d_in[1];
    const float* gru_state = (const float*)d_in[2];
    const float* mfwd      = (const float*)d_in[3];
    const float* mbwd      = (const float*)d_in[4];
    const float* inproj_W  = (const float*)d_in[5];
    const float* inproj_b  = (const float*)d_in[6];
    const float* m_inW     = (const float*)d_in[7];
    const float* m_dtW     = (const float*)d_in[8];
    const float* m_dtb     = (const float*)d_in[9];
    const float* m_BW      = (const float*)d_in[10];
    const float* m_CW      = (const float*)d_in[11];
    const float* m_Alog    = (const float*)d_in[12];
    const float* m_D       = (const float*)d_in[13];
    const float* m_rope    = (const float*)d_in[14];
    const float* m_outW    = (const float*)d_in[15];
    const float* gru_Wz    = (const float*)d_in[16];
    const float* gru_bz    = (const float*)d_in[17];
    const float* gru_Wr    = (const float*)d_in[18];
    const float* gru_br    = (const float*)d_in[19];
    const float* gru_Wh    = (const float*)d_in[20];
    const float* gru_bh    = (const float*)d_in[21];
    const float* peer_qW   = (const float*)d_in[22];
    const float* keysA     = (const float*)d_in[23];
    const float* keysB     = (const float*)d_in[24];
    const float* eW1       = (const float*)d_in[25];
    const float* eb1       = (const float*)d_in[26];
    const float* eW2       = (const float*)d_in[27];
    const float* eb2       = (const float*)d_in[28];
    float* out = (float*)d_out;

    unsigned int *ki, *ko, *vi, *vo;
    void* tmp;
    float *xbuf, *ysbuf, *ctxbuf;
    cudaGetSymbolAddress((void**)&ki, g_keys);
    cudaGetSymbolAddress((void**)&ko, g_keys2);
    cudaGetSymbolAddress((void**)&vi, g_idx);
    cudaGetSymbolAddress((void**)&vo, g_idx2);
    cudaGetSymbolAddress(&tmp, g_cubtemp);
    cudaGetSymbolAddress((void**)&xbuf, g_x);
    cudaGetSymbolAddress((void**)&ysbuf, g_ys);
    cudaGetSymbolAddress((void**)&ctxbuf, g_ctx);

    prep_kernel<<<NTOT / 256, 256>>>(grad, ki, vi);

    // FULL 32-bit stable sort: the permutation must exactly match
    // jnp.argsort(|g|). (R5 lesson: truncating low key bits swaps near-tied
    // elements whose sharpness features differ O(1) -> ctx errors ~1e-2.)
    size_t temp_bytes = sizeof(g_cubtemp);
    cub::DeviceRadixSort::SortPairs(tmp, temp_bytes, ki, ko, vi, vo, NTOT, 0, 32,
                                    (cudaStream_t)0);

    xproj_kernel<<<NTOT / 256, 256>>>(grad, sharp, vo, inproj_W, inproj_b, xbuf);

    scan_kernel<<<dim3(NCH, 2), 256>>>(xbuf, m_inW, m_dtW, m_dtb, m_BW, m_CW,
                                       m_Alog, m_rope, mfwd, mbwd, ysbuf,
                                       out + 5 * NTOT);

    post_kernel<<<NTOT / 256, 256>>>(xbuf, ysbuf, vo, m_inW, m_D, m_outW, ctxbuf);

    gp_kernel<<<NTOT / 256, 256>>>(grad, sharp, gru_state, ctxbuf,
                                   gru_Wz, gru_bz, gru_Wr, gru_br, gru_Wh, gru_bh,
                                   peer_qW, keysA, keysB, eW1, eb1, eW2, eb2, out);

    (void)in_sizes; (void)n_in; (void)out_size;
}

// round 7
// speedup vs baseline: 1.8122x; 1.2307x over previous
#include <cuda_runtime.h>
#include <cuda_bf16.h>
#include <cub/cub.cuh>
#include <math.h>

#define NTOT 65536
#define L_CH 256
#define WARMUP 64
#define NCH (NTOT / L_CH)   // 256

// ---------------- static scratch (no allocations allowed) ----------------
__device__ unsigned int g_keys[NTOT];
__device__ unsigned int g_keys2[NTOT];
__device__ unsigned int g_idx[NTOT];
__device__ unsigned int g_idx2[NTOT];
__device__ unsigned char g_cubtemp[1 << 23];   // 8 MB, plenty for 64K pairs
__device__ float g_x[NTOT * 8];                // sorted-order features
__device__ float g_ys[2 * NTOT * 16];          // raw scan outputs (dir, sortedpos, i)
__device__ float g_ctx[2 * NTOT * 8];          // fwd/bwd ctx in ORIGINAL order

// ---------------- kernel 1: sort keys ----------------
__global__ void prep_kernel(const float* __restrict__ g,
                            unsigned int* __restrict__ keys,
                            unsigned int* __restrict__ vals) {
    int n = blockIdx.x * blockDim.x + threadIdx.x;
    keys[n] = __float_as_uint(g[n]) & 0x7fffffffu;  // |g| bits sort as uint
    vals[n] = (unsigned)n;
}

// ---------------- kernel 2: x = [gs, ss] @ inproj_W.T + b (sorted order) ----------------
__global__ void xproj_kernel(const float* __restrict__ g, const float* __restrict__ s,
                             const unsigned int* __restrict__ sidx,
                             const float* __restrict__ W, const float* __restrict__ b,
                             float* __restrict__ x) {
    int k = blockIdx.x * blockDim.x + threadIdx.x;
    int o = sidx[k];
    float gv = g[o], sv = s[o];
#pragma unroll
    for (int m = 0; m < 8; m++)
        x[k * 8 + m] = fmaf(gv, W[m * 2 + 0], fmaf(sv, W[m * 2 + 1], b[m]));
}

// ---------------- kernel 3: chunked warmup Mamba scan (both directions) ----------------
// Per 16-step tile:
//   A) parallel projections (xb, dt, B[, C]) with 256 threads as (t,c)
//   B/C) two 8-step halves: coefficient precompute (MUFU sincos + fast div,
//        off the dependent chain, only 8 live coef regs) then the tight
//        recurrence: shfl + 2 FMA (+ STS h when producing output)
//   D) parallel y = sum_j h*C from shared (output tiles only)
// x for the NEXT tile is prefetched into registers to hide L2 latency.
__global__ void __launch_bounds__(256) scan_kernel(
    const float* __restrict__ x,
    const float* __restrict__ inW,   // (2,32,8)
    const float* __restrict__ dtW,   // (2,16,16)
    const float* __restrict__ dtb,   // (2,16)
    const float* __restrict__ BW,    // (2,16,16)
    const float* __restrict__ CW,    // (2,16,16)
    const float* __restrict__ Alog,  // (2,16,16)
    const float* __restrict__ rope,  // (2,16,16)
    const float* __restrict__ h0f, const float* __restrict__ h0b,
    float* __restrict__ ys,          // (2,N,16)
    float* __restrict__ hfin)        // 512 floats: new_fwd then new_bwd
{
    const int dir = blockIdx.y;
    const int chunk = blockIdx.x;
    const int tid = threadIdx.x;
    const int i = tid >> 4, j = tid & 15;
    const int lane = tid & 31;
    const int srcRot = (lane & 16) | ((lane + 15) & 15);  // j-1 mod 16 within 16-lane group

    __shared__ float s_inWx[8][16];   // [m][i]
    __shared__ float s_dtWT[16][16];  // [k][i]
    __shared__ float s_BWT[16][16];   // [k][j]
    __shared__ float s_CWT[16][16];
    __shared__ float s_dtb[16];
    __shared__ float sx[16][8];
    __shared__ float sxb[16][16];
    __shared__ float sdt[16][16];
    __shared__ float sdxb[16][16];
    __shared__ float sB[16][16];
    __shared__ float sC[16][16];
    __shared__ float sh[16][16][17];  // padded: conflict-free write(t,i,j) & read(j-loop)

    if (tid < 128) { int m = tid >> 4, c = tid & 15; s_inWx[m][c] = inW[dir * 256 + c * 8 + m]; }
    { int k = tid >> 4, c = tid & 15;
      s_dtWT[k][c] = dtW[dir * 256 + c * 16 + k];
      s_BWT[k][c]  = BW [dir * 256 + c * 16 + k];
      s_CWT[k][c]  = CW [dir * 256 + c * 16 + k]; }
    if (tid < 16) s_dtb[tid] = dtb[dir * 16 + tid];

    const float Ac = -__expf(Alog[dir * 256 + tid]);
    const float Rc = rope[dir * 256 + tid];

    int g0 = chunk * L_CH - WARMUP;
    float h;
    if (g0 <= 0) { g0 = 0; h = (dir == 0 ? h0f : h0b)[tid]; }  // exact initial state
    else h = 0.0f;                                             // warmup (state decays)
    const int gend = (chunk + 1) * L_CH;
    const int outStart = chunk * L_CH;

    const int xt = tid >> 3, xm = tid & 7;   // staging role for tid<128
    float xr = 0.0f;
    if (tid < 128) {
        int p = (dir == 0) ? (g0 + xt) : (NTOT - 1 - (g0 + xt));
        xr = x[p * 8 + xm];
    }
    __syncthreads();

    for (int base = g0; base < gend; base += 16) {
        const bool doOut = (base >= outStart);   // block-uniform
        if (tid < 128) sx[xt][xm] = xr;
        __syncthreads();                                         // S1
        {   // xb projection
            int t = tid >> 4, c = tid & 15;
            float acc = 0.0f;
#pragma unroll
            for (int m = 0; m < 8; m++) acc = fmaf(sx[t][m], s_inWx[m][c], acc);
            sxb[t][c] = acc;
        }
        __syncthreads();                                         // S2
        {   // dt / B (+C for output tiles) projections
            int t = tid >> 4, c = tid & 15;
            float u = s_dtb[c], bv = 0.0f;
#pragma unroll
            for (int k = 0; k < 16; k++) {
                float xbk = sxb[t][k];
                u  = fmaf(xbk, s_dtWT[k][c], u);
                bv = fmaf(xbk, s_BWT[k][c], bv);
            }
            // fast softplus: MUFU exp+log; u>15 branch keeps overflow exact
            float dt = (u > 15.0f) ? u : __logf(1.0f + __expf(u));
            sdt[t][c] = dt;
            sdxb[t][c] = dt * sxb[t][c];
            sB[t][c] = bv;
            if (doOut) {
                float cv = 0.0f;
#pragma unroll
                for (int k = 0; k < 16; k++) cv = fmaf(sxb[t][k], s_CWT[k][c], cv);
                sC[t][c] = cv;
            }
        }
        // prefetch next tile's x (latency hidden behind phases B/C/D)
        if (tid < 128 && base + 16 < gend) {
            int p = (dir == 0) ? (base + 16 + xt) : (NTOT - 1 - (base + 16 + xt));
            xr = x[p * 8 + xm];
        }
        __syncthreads();                                         // S3
        // ---- phases B+C in two 8-step halves (low register pressure) ----
#pragma unroll
        for (int half = 0; half < 2; half++) {
            float ca[8], cb[8], db[8];
#pragma unroll
            for (int tt = 0; tt < 8; tt++) {
                int t = half * 8 + tt;
                float dt = sdt[t][i];
                float ph = dt * Rc;
                float sn, cs;
                __sincosf(ph, &sn, &cs);        // |ph| small: abs err ~2^-21
                float xA  = dt * Ac;
                float num = fmaf(0.5f, xA, 1.0f);
                float den = fmaf(-0.5f, xA, 1.0f + 1e-8f);
                float t_r = __fdividef(num, den);
                ca[tt] = cs * t_r;
                cb[tt] = sn * t_r;
                db[tt] = sdxb[t][i] * sB[t][j];
            }
            if (doOut) {
#pragma unroll
                for (int tt = 0; tt < 8; tt++) {
                    float hm1 = __shfl_sync(0xffffffffu, h, srcRot);
                    h = fmaf(ca[tt], h, fmaf(-cb[tt], hm1, db[tt]));
                    sh[half * 8 + tt][i][j] = h;
                }
            } else {
#pragma unroll
                for (int tt = 0; tt < 8; tt++) {
                    float hm1 = __shfl_sync(0xffffffffu, h, srcRot);
                    h = fmaf(ca[tt], h, fmaf(-cb[tt], hm1, db[tt]));
                }
            }
        }
        if (doOut) {
            __syncthreads();                                     // S4
            // ---- phase D: y = sum_j h*C, fully parallel ----
            int t = tid >> 4, ii = tid & 15;
            float acc = 0.0f;
#pragma unroll
            for (int jj = 0; jj < 16; jj++)
                acc = fmaf(sh[t][ii][jj], sC[t][jj], acc);
            int p = (dir == 0) ? (base + t) : (NTOT - 1 - (base + t));
            ys[((size_t)dir * NTOT + p) * 16 + ii] = acc;
        }
        // no trailing sync: next tile's S1 orders all cross-tile hazards
        // (every smem buffer is re-written only after a later barrier that
        //  all readers have already passed).
    }
    if (chunk == NCH - 1) hfin[dir * 256 + tid] = h;  // final states (outputs)
}

// ---------------- kernel 4: epilogue projections + scatter to original order ----------------
__global__ void post_kernel(const float* __restrict__ x, const float* __restrict__ ys,
                            const unsigned int* __restrict__ sidx,
                            const float* __restrict__ inW, const float* __restrict__ D,
                            const float* __restrict__ outW, float* __restrict__ ctx) {
    int k = blockIdx.x * blockDim.x + threadIdx.x;
    float4 xv0 = ((const float4*)x)[k * 2 + 0];
    float4 xv1 = ((const float4*)x)[k * 2 + 1];
    float xv[8] = {xv0.x, xv0.y, xv0.z, xv0.w, xv1.x, xv1.y, xv1.z, xv1.w};
    int o = sidx[k];
#pragma unroll
    for (int d = 0; d < 2; d++) {
        float yv[16];
#pragma unroll
        for (int q = 0; q < 4; q++) {
            float4 y4 = ((const float4*)ys)[((size_t)d * NTOT + k) * 4 + q];
            yv[q * 4 + 0] = y4.x; yv[q * 4 + 1] = y4.y;
            yv[q * 4 + 2] = y4.z; yv[q * 4 + 3] = y4.w;
        }
        float out[8];
#pragma unroll
        for (int m = 0; m < 8; m++) out[m] = 0.0f;
#pragma unroll
        for (int ii = 0; ii < 16; ii++) {
            float xb = 0.0f, z = 0.0f;
#pragma unroll
            for (int m = 0; m < 8; m++) {
                xb = fmaf(xv[m], inW[d * 256 + ii * 8 + m], xb);
                z  = fmaf(xv[m], inW[d * 256 + (16 + ii) * 8 + m], z);
            }
            float sg = __fdividef(1.0f, 1.0f + __expf(-z));
            float yi = fmaf(yv[ii], z * sg, D[d * 16 + ii] * xb);
#pragma unroll
            for (int m = 0; m < 8; m++)
                out[m] = fmaf(yi, outW[d * 128 + m * 16 + ii], out[m]);
        }
        float4* cbase = (float4*)&ctx[((size_t)d * NTOT + o) * 8];
        cbase[0] = make_float4(out[0], out[1], out[2], out[3]);
        cbase[1] = make_float4(out[4], out[5], out[6], out[7]);
    }
}

// ---------------- kernel 5: GRU + PEER routing/experts + final combine ----------------
__global__ void __launch_bounds__(256) gp_kernel(
    const float* __restrict__ g, const float* __restrict__ s,
    const float* __restrict__ gru0, const float* __restrict__ ctx,
    const float* __restrict__ Wz, const float* __restrict__ bz,
    const float* __restrict__ Wr, const float* __restrict__ br,
    const float* __restrict__ Wh, const float* __restrict__ bh,
    const float* __restrict__ qW, const float* __restrict__ kA, const float* __restrict__ kB,
    const float* __restrict__ eW1, const float* __restrict__ eb1,
    const float* __restrict__ eW2, const float* __restrict__ eb2,
    float* __restrict__ out) {
    __shared__ float sWz[88], sWr[88], sWh[88], sbz[4], sbr[4], sbh[4];
    __shared__ float sqW[704];       // (4,8,22)
    __shared__ float skA[192], skB[192];
    __shared__ float seW1[144 * 17], seb1[144 * 17], seW2[144 * 17];  // pad vs bank conflicts
    __shared__ float seb2[144];

    int tid = threadIdx.x;
    for (int q = tid; q < 88; q += 256) { sWz[q] = Wz[q]; sWr[q] = Wr[q]; sWh[q] = Wh[q]; }
    if (tid < 4) { sbz[tid] = bz[tid]; sbr[tid] = br[tid]; sbh[tid] = bh[tid]; }
    for (int q = tid; q < 704; q += 256) sqW[q] = qW[q];
    for (int q = tid; q < 192; q += 256) { skA[q] = kA[q]; skB[q] = kB[q]; }
    for (int q = tid; q < 2304; q += 256) {
        int e = q >> 4, eh = q & 15;
        seW1[e * 17 + eh] = eW1[q];
        seb1[e * 17 + eh] = eb1[q];
        seW2[e * 17 + eh] = eW2[q];
    }
    for (int q = tid; q < 144; q += 256) seb2[q] = eb2[q];
    __syncthreads();

    int n = blockIdx.x * blockDim.x + tid;
    float gv = g[n], sv = s[n];
    float xin[18];
    xin[0] = gv; xin[1] = sv;
#pragma unroll
    for (int m = 0; m < 8; m++) { xin[2 + m] = ctx[(size_t)n * 8 + m]; xin[10 + m] = ctx[(size_t)(NTOT + n) * 8 + m]; }
    float hv[4];
#pragma unroll
    for (int c = 0; c < 4; c++) hv[c] = gru0[n * 4 + c];

    float zg[4], rr[4];
#pragma unroll
    for (int c = 0; c < 4; c++) {
        float az = sbz[c], ar = sbr[c];
#pragma unroll
        for (int q = 0; q < 18; q++) { az = fmaf(xin[q], sWz[c * 22 + q], az); ar = fmaf(xin[q], sWr[c * 22 + q], ar); }
#pragma unroll
        for (int q = 0; q < 4; q++) { az = fmaf(hv[q], sWz[c * 22 + 18 + q], az); ar = fmaf(hv[q], sWr[c * 22 + 18 + q], ar); }
        zg[c] = __fdividef(1.0f, 1.0f + __expf(-az));
        rr[c] = __fdividef(1.0f, 1.0f + __expf(-ar));
    }
    float ng[4];
#pragma unroll
    for (int c = 0; c < 4; c++) {
        float ah = sbh[c];
#pragma unroll
        for (int q = 0; q < 18; q++) ah = fmaf(xin[q], sWh[c * 22 + q], ah);
#pragma unroll
        for (int q = 0; q < 4; q++) ah = fmaf(rr[q] * hv[q], sWh[c * 22 + 18 + q], ah);
        float ht = tanhf(ah);
        ng[c] = fmaf(zg[c], ht - hv[c], hv[c]);
        out[NTOT + n * 4 + c] = ng[c];
    }

    float pin[22];
#pragma unroll
    for (int c = 0; c < 4; c++) pin[c] = ng[c];
#pragma unroll
    for (int m = 0; m < 16; m++) pin[4 + m] = xin[2 + m];
    pin[20] = gv; pin[21] = sv;

    float tot = 0.0f;
#pragma unroll
    for (int hd = 0; hd < 4; hd++) {
        float q[8];
#pragma unroll
        for (int m = 0; m < 8; m++) {
            float a = 0.0f;
#pragma unroll
            for (int qq = 0; qq < 22; qq++) a = fmaf(pin[qq], sqW[hd * 176 + m * 22 + qq], a);
            q[m] = a;
        }
        int ia = 0, ib = 0;
        float ba = -3.4e38f, bb = -3.4e38f;
#pragma unroll
        for (int p = 0; p < 12; p++) {
            float sa = q[0] * skA[hd * 48 + p * 4 + 0];
            sa = fmaf(q[1], skA[hd * 48 + p * 4 + 1], sa);
            sa = fmaf(q[2], skA[hd * 48 + p * 4 + 2], sa);
            sa = fmaf(q[3], skA[hd * 48 + p * 4 + 3], sa);
            if (sa > ba) { ba = sa; ia = p; }
            float sb = q[4] * skB[hd * 48 + p * 4 + 0];
            sb = fmaf(q[5], skB[hd * 48 + p * 4 + 1], sb);
            sb = fmaf(q[6], skB[hd * 48 + p * 4 + 2], sb);
            sb = fmaf(q[7], skB[hd * 48 + p * 4 + 3], sb);
            if (sb > bb) { bb = sb; ib = p; }
        }
        int e = ia * 12 + ib;
        float acc = seb2[e];
#pragma unroll
        for (int eh = 0; eh < 16; eh++) {
            float z1 = fmaf(seW1[e * 17 + eh], gv, seb1[e * 17 + eh]);
            z1 = fmaxf(z1, 0.0f);
            acc = fmaf(seW2[e * 17 + eh], z1, acc);
        }
        tot += acc;
    }
    out[n] = fmaf(0.1f * 0.25f, tot, gv);  // g + RESCALE * total/NH
}

// ---------------- launch ----------------
extern "C" void kernel_launch(void* const* d_in, const int* in_sizes, int n_in,
                              void* d_out, int out_size) {
    const float* grad      = (const float*)d_in[0];
    const float* sharp     = (const float*)d_in[1];
    const float* gru_state = (const float*)d_in[2];
    const float* mfwd      = (const float*)d_in[3];
    const float* mbwd      = (const float*)d_in[4];
    const float* inproj_W  = (const float*)d_in[5];
    const float* inproj_b  = (const float*)d_in[6];
    const float* m_inW     = (const float*)d_in[7];
    const float* m_dtW     = (const float*)d_in[8];
    const float* m_dtb     = (const float*)d_in[9];
    const float* m_BW      = (const float*)d_in[10];
    const float* m_CW      = (const float*)d_in[11];
    const float* m_Alog    = (const float*)d_in[12];
    const float* m_D       = (const float*)d_in[13];
    const float* m_rope    = (const float*)d_in[14];
    const float* m_outW    = (const float*)d_in[15];
    const float* gru_Wz    = (const float*)d_in[16];
    const float* gru_bz    = (const float*)d_in[17];
    const float* gru_Wr    = (const float*)d_in[18];
    const float* gru_br    = (const float*)d_in[19];
    const float* gru_Wh    = (const float*)d_in[20];
    const float* gru_bh    = (const float*)d_in[21];
    const float* peer_qW   = (const float*)d_in[22];
    const float* keysA     = (const float*)d_in[23];
    const float* keysB     = (const float*)d_in[24];
    const float* eW1       = (const float*)d_in[25];
    const float* eb1       = (const float*)d_in[26];
    const float* eW2       = (const float*)d_in[27];
    const float* eb2       = (const float*)d_in[28];
    float* out = (float*)d_out;

    unsigned int *ki, *ko, *vi, *vo;
    void* tmp;
    float *xbuf, *ysbuf, *ctxbuf;
    cudaGetSymbolAddress((void**)&ki, g_keys);
    cudaGetSymbolAddress((void**)&ko, g_keys2);
    cudaGetSymbolAddress((void**)&vi, g_idx);
    cudaGetSymbolAddress((void**)&vo, g_idx2);
    cudaGetSymbolAddress(&tmp, g_cubtemp);
    cudaGetSymbolAddress((void**)&xbuf, g_x);
    cudaGetSymbolAddress((void**)&ysbuf, g_ys);
    cudaGetSymbolAddress((void**)&ctxbuf, g_ctx);

    prep_kernel<<<NTOT / 256, 256>>>(grad, ki, vi);

    // FULL 32-bit stable sort: the permutation must exactly match
    // jnp.argsort(|g|). (R5 lesson: truncating low key bits swaps near-tied
    // elements whose sharpness features differ O(1) -> ctx errors ~1e-2.)
    size_t temp_bytes = sizeof(g_cubtemp);
    cub::DeviceRadixSort::SortPairs(tmp, temp_bytes, ki, ko, vi, vo, NTOT, 0, 32,
                                    (cudaStream_t)0);

    xproj_kernel<<<NTOT / 256, 256>>>(grad, sharp, vo, inproj_W, inproj_b, xbuf);

    scan_kernel<<<dim3(NCH, 2), 256>>>(xbuf, m_inW, m_dtW, m_dtb, m_BW, m_CW,
                                       m_Alog, m_rope, mfwd, mbwd, ysbuf,
                                       out + 5 * NTOT);

    post_kernel<<<NTOT / 256, 256>>>(xbuf, ysbuf, vo, m_inW, m_D, m_outW, ctxbuf);

    gp_kernel<<<NTOT / 256, 256>>>(grad, sharp, gru_state, ctxbuf,
                                   gru_Wz, gru_bz, gru_Wr, gru_br, gru_Wh, gru_bh,
                                   peer_qW, keysA, keysB, eW1, eb1, eW2, eb2, out);

    (void)in_sizes; (void)n_in; (void)out_size;
}